// round 16
// baseline (speedup 1.0000x reference)
#include <cuda_runtime.h>
#include <cuda_bf16.h>

#define NN      50000
#define ECNT    1600000
#define INDIM   128
#define D1      96
#define GG      512
#define HID     512
#define NEG     0.2f
#define EPSV    1e-16f
#define DEGMAX  128
#define NMAX    20000
#define ESTORE  4096

// ---------------- device scratch ----------------
__device__ int   g_counts[NN];
__device__ int   g_ssrc2[NN * DEGMAX];
__device__ int   g_firstidx[GG];
__device__ int   g_poolslot[NN];
__device__ int   g_needed[NN];
__device__ int   g_list[NMAX];
__device__ int   g_ncnt;
__device__ int   g_task;
__device__ int   g_barArrive;
__device__ volatile unsigned g_barGen;

__device__ __align__(16) float g_xl1[NN * D1];
__device__ __align__(16) float g_xr1[NN * D1];
__device__ __align__(16) float g_h1 [NN * D1];
__device__ __align__(16) float g_xl2[NN * D1];
__device__ __align__(16) float g_pooled[GG * 192];

__device__ __forceinline__ float leaky(float t) { return t > 0.f ? t : NEG * t; }

__device__ __forceinline__ void gridsync(int nb) {
    __syncthreads();
    if (threadIdx.x == 0) {
        __threadfence();
        unsigned gen = g_barGen;
        if (atomicAdd(&g_barArrive, 1) == nb - 1) {
            g_barArrive = 0;
            __threadfence();
            g_barGen = gen + 1;
        } else {
            while (g_barGen == gen) __nanosleep(64);
        }
        __threadfence();
    }
    __syncthreads();
}

// ---------------- GEMM tile helpers ----------
__device__ void gemm_tile_full(const float* __restrict__ A, const float* __restrict__ B,
                               const float* __restrict__ bias, float* __restrict__ C,
                               int tile, int M, int K,
                               float (*As)[132], float (*Bs)[96]) {
    int tx = threadIdx.x & 15;
    int ty = threadIdx.x >> 4;
    int rowBase = tile * 128;
    float acc[8][6];
#pragma unroll
    for (int r = 0; r < 8; r++)
#pragma unroll
        for (int c = 0; c < 6; c++) acc[r][c] = 0.f;
    int lm = threadIdx.x >> 1;
    int lk = (threadIdx.x & 1) * 4;
    for (int kt = 0; kt < K; kt += 8) {
        int gr = rowBase + lm;
        float4 av = (gr < M) ? *(const float4*)&A[(long)gr * K + kt + lk]
                             : make_float4(0.f, 0.f, 0.f, 0.f);
        As[lk + 0][lm] = av.x; As[lk + 1][lm] = av.y;
        As[lk + 2][lm] = av.z; As[lk + 3][lm] = av.w;
#pragma unroll
        for (int j = 0; j < 3; j++) {
            int idx = threadIdx.x + 256 * j;
            Bs[idx / 96][idx % 96] = B[(kt + idx / 96) * 96 + idx % 96];
        }
        __syncthreads();
#pragma unroll
        for (int k = 0; k < 8; k++) {
            float a[8], bb[6];
#pragma unroll
            for (int r = 0; r < 8; r++) a[r] = As[k][ty + 16 * r];
#pragma unroll
            for (int c = 0; c < 6; c++) bb[c] = Bs[k][tx + 16 * c];
#pragma unroll
            for (int r = 0; r < 8; r++)
#pragma unroll
                for (int c = 0; c < 6; c++) acc[r][c] = fmaf(a[r], bb[c], acc[r][c]);
        }
        __syncthreads();
    }
#pragma unroll
    for (int r = 0; r < 8; r++) {
        int row = rowBase + ty + 16 * r;
        if (row < M) {
#pragma unroll
            for (int c = 0; c < 6; c++)
                C[(long)row * 96 + tx + 16 * c] = acc[r][c] + bias[tx + 16 * c];
        }
    }
}

__device__ void gemm_tile_gather(const float* __restrict__ A, const float* __restrict__ B,
                                 const float* __restrict__ bias, float* __restrict__ C,
                                 int tile, int cnt, int K,
                                 float (*As)[132], float (*Bs)[96], int* rows) {
    int tx = threadIdx.x & 15;
    int ty = threadIdx.x >> 4;
    int rowBase = tile * 128;
    if (threadIdx.x < 128) {
        int r = rowBase + threadIdx.x;
        rows[threadIdx.x] = (r < cnt) ? g_list[r] : -1;
    }
    __syncthreads();
    float acc[8][6];
#pragma unroll
    for (int r = 0; r < 8; r++)
#pragma unroll
        for (int c = 0; c < 6; c++) acc[r][c] = 0.f;
    int lm = threadIdx.x >> 1;
    int lk = (threadIdx.x & 1) * 4;
    for (int kt = 0; kt < K; kt += 8) {
        int nd = rows[lm];
        float4 av = (nd >= 0) ? *(const float4*)&A[(long)nd * K + kt + lk]
                              : make_float4(0.f, 0.f, 0.f, 0.f);
        As[lk + 0][lm] = av.x; As[lk + 1][lm] = av.y;
        As[lk + 2][lm] = av.z; As[lk + 3][lm] = av.w;
#pragma unroll
        for (int j = 0; j < 3; j++) {
            int idx = threadIdx.x + 256 * j;
            Bs[idx / 96][idx % 96] = B[(kt + idx / 96) * 96 + idx % 96];
        }
        __syncthreads();
#pragma unroll
        for (int k = 0; k < 8; k++) {
            float a[8], bb[6];
#pragma unroll
            for (int r = 0; r < 8; r++) a[r] = As[k][ty + 16 * r];
#pragma unroll
            for (int c = 0; c < 6; c++) bb[c] = Bs[k][tx + 16 * c];
#pragma unroll
            for (int r = 0; r < 8; r++)
#pragma unroll
                for (int c = 0; c < 6; c++) acc[r][c] = fmaf(a[r], bb[c], acc[r][c]);
        }
        __syncthreads();
    }
#pragma unroll
    for (int r = 0; r < 8; r++) {
        int nd = rows[ty + 16 * r];
        if (nd >= 0) {
#pragma unroll
            for (int c = 0; c < 6; c++)
                C[(long)nd * 96 + tx + 16 * c] = acc[r][c] + bias[tx + 16 * c];
        }
    }
}

// ================= KERNEL 1: build (unchanged) =====================
__global__ __launch_bounds__(256)
void k_build(const float* __restrict__ x,
             const float* __restrict__ Wl1, const float* __restrict__ bl1,
             const float* __restrict__ Wr1, const float* __restrict__ br1,
             const int* __restrict__ ei, const int* __restrict__ batch, int nb) {
    __shared__ float sh[1824];
    __shared__ int rows[128];
    __shared__ int s_task;
    float (*As)[132] = (float(*)[132])sh;
    float (*Bs)[96]  = (float(*)[96])(sh + 1056);

    int tid = threadIdx.x;
    int gtid = blockIdx.x * blockDim.x + tid;
    int gstride = nb * blockDim.x;

    for (int i = gtid; i < NN; i += gstride) {
        g_counts[i] = 0;
        int b = batch[i];
        int pooled = (i == 0) || (batch[i - 1] != b);
        g_needed[i] = pooled;
        if (pooled) {
            g_firstidx[b] = i;
            g_poolslot[i] = b;
            g_list[b] = i;
        } else {
            g_poolslot[i] = -1;
        }
    }
    if (gtid == 0) { g_ncnt = GG; g_task = 0; }
    gridsync(nb);

    {
        const int4* s4 = (const int4*)ei;
        const int4* d4 = (const int4*)(ei + ECNT);
        for (int e4 = gtid; e4 < ECNT / 4; e4 += gstride) {
            int4 dd = d4[e4];
            int4 ss = s4[e4];
            int d[4] = {dd.x, dd.y, dd.z, dd.w};
            int s[4] = {ss.x, ss.y, ss.z, ss.w};
#pragma unroll
            for (int k = 0; k < 4; k++) {
                if (g_poolslot[d[k]] >= 0) {
                    if (atomicExch(&g_needed[s[k]], 1) == 0) {
                        int p = atomicAdd(&g_ncnt, 1);
                        if (p < NMAX) g_list[p] = s[k];
                    }
                }
            }
        }
    }
    gridsync(nb);

    {
        int cnt = min(g_ncnt, NMAX);
        const int T1 = (NN + 127) / 128;
        int T2 = (cnt + 127) / 128;
        const int SC = (ECNT + ESTORE - 1) / ESTORE;
        int total = T1 + T2 + SC;
        const int4* s4 = (const int4*)ei;
        const int4* d4 = (const int4*)(ei + ECNT);
        for (;;) {
            __syncthreads();
            if (tid == 0) s_task = atomicAdd(&g_task, 1);
            __syncthreads();
            int t = s_task;
            if (t >= total) break;
            if (t < T1) {
                gemm_tile_full(x, Wl1, bl1, g_xl1, t, NN, INDIM, As, Bs);
            } else if (t < T1 + T2) {
                gemm_tile_gather(x, Wr1, br1, g_xr1, t - T1, cnt, INDIM, As, Bs, rows);
            } else {
                int base4 = (t - T1 - T2) * (ESTORE / 4);
#pragma unroll
                for (int k = 0; k < 4; k++) {
                    int e4 = base4 + k * 256 + tid;
                    if (e4 < ECNT / 4) {
                        int4 dd = d4[e4];
                        int4 ss = s4[e4];
                        int d[4] = {dd.x, dd.y, dd.z, dd.w};
                        int s[4] = {ss.x, ss.y, ss.z, ss.w};
#pragma unroll
                        for (int j = 0; j < 4; j++) {
                            if (g_needed[d[j]]) {
                                int p = atomicAdd(&g_counts[d[j]], 1);
                                if (p < DEGMAX) g_ssrc2[d[j] * DEGMAX + p] = s[j];
                            }
                        }
                    }
                }
            }
        }
    }
}

// ================= KERNEL 2: GNN — block-per-dst gat1 =======================
__global__ __launch_bounds__(256, 3)
void k_gnn(const float* __restrict__ att1, const float* __restrict__ bias1,
           const float* __restrict__ Wl2,  const float* __restrict__ bl2,
           const float* __restrict__ Wr2,  const float* __restrict__ br2,
           const float* __restrict__ att2, const float* __restrict__ bias2,
           const float* __restrict__ Wfc1, const float* __restrict__ bfc1,
           const float* __restrict__ Wfc2, const float* __restrict__ bfc2,
           float* __restrict__ out, int nb) {
    __shared__ float sh[1680];
    // gat1 views
    float (*red)[8][16] = (float(*)[8][16])sh;       // 1024 floats
    float* h1sh         = sh + 1024;                 // 96
    // fc8 views
    float (*pr)[192]  = (float(*)[192])sh;
    float (*part)[16] = (float(*)[16])(sh + 1536);
    float* slog       = sh + 1664;

    int tid = threadIdx.x;
    int wid = tid >> 5, l = tid & 31;
    const unsigned FULL = 0xffffffffu;

    // ---- PHASE gat1 + fused xl2: ONE BLOCK PER DESTINATION ----
    // 32 edge slots (grp = tid>>3) x 8 lanes (u = tid&7); all edges' gathers
    // are in flight simultaneously -> one L2 round-trip per destination.
    {
        int cnt = min(g_ncnt, NMAX);
        int u = tid & 7;
        int grp = tid >> 3;
        const float4* att4 = (const float4*)att1;
        float4 A0 = att4[u], A1 = att4[8 + u], A2 = att4[16 + u];
        const float4* xl4 = (const float4*)g_xl1;
        const float4* xr4 = (const float4*)g_xr1;

        for (int gw = blockIdx.x; gw < cnt; gw += nb) {
            int dst = g_list[gw];
            float4 q0 = xr4[(long)dst * 24 + u];
            float4 q1 = xr4[(long)dst * 24 + 8 + u];
            float4 q2 = xr4[(long)dst * 24 + 16 + u];

            int en = min(g_counts[dst], DEGMAX);
            int tot = en + 1;  // + self-loop (slot 0)
            const int* lst = &g_ssrc2[dst * DEGMAX];

            float d0 = 0.f, d1 = 0.f, d2 = 0.f;
            float4 s0 = {0,0,0,0}, s1 = {0,0,0,0}, s2 = {0,0,0,0};

            for (int base = 0; base < tot; base += 32) {
                int eidx = base + grp;
                bool valid = eidx < tot;
                int src = (valid && eidx > 0) ? lst[eidx - 1] : dst;
                const float4* row = xl4 + (long)src * 24;
                float4 v0 = row[u], v1 = row[8 + u], v2 = row[16 + u];
                float p0 = leaky(v0.x + q0.x) * A0.x + leaky(v0.y + q0.y) * A0.y
                         + leaky(v0.z + q0.z) * A0.z + leaky(v0.w + q0.w) * A0.w;
                float p1 = leaky(v1.x + q1.x) * A1.x + leaky(v1.y + q1.y) * A1.y
                         + leaky(v1.z + q1.z) * A1.z + leaky(v1.w + q1.w) * A1.w;
                float p2 = leaky(v2.x + q2.x) * A2.x + leaky(v2.y + q2.y) * A2.y
                         + leaky(v2.z + q2.z) * A2.z + leaky(v2.w + q2.w) * A2.w;
#pragma unroll
                for (int o = 4; o; o >>= 1) {
                    p0 += __shfl_xor_sync(FULL, p0, o);
                    p1 += __shfl_xor_sync(FULL, p1, o);
                    p2 += __shfl_xor_sync(FULL, p2, o);
                }
                float e0 = valid ? __expf(p0) : 0.f;
                float e1 = valid ? __expf(p1) : 0.f;
                float e2 = valid ? __expf(p2) : 0.f;
                d0 += e0; d1 += e1; d2 += e2;
                s0.x = fmaf(e0, v0.x, s0.x); s0.y = fmaf(e0, v0.y, s0.y);
                s0.z = fmaf(e0, v0.z, s0.z); s0.w = fmaf(e0, v0.w, s0.w);
                s1.x = fmaf(e1, v1.x, s1.x); s1.y = fmaf(e1, v1.y, s1.y);
                s1.z = fmaf(e1, v1.z, s1.z); s1.w = fmaf(e1, v1.w, s1.w);
                s2.x = fmaf(e2, v2.x, s2.x); s2.y = fmaf(e2, v2.y, s2.y);
                s2.z = fmaf(e2, v2.z, s2.z); s2.w = fmaf(e2, v2.w, s2.w);
            }

            // reduce across the 4 edge-slots within each warp
#pragma unroll
            for (int o = 8; o <= 16; o <<= 1) {
                d0 += __shfl_xor_sync(FULL, d0, o);
                d1 += __shfl_xor_sync(FULL, d1, o);
                d2 += __shfl_xor_sync(FULL, d2, o);
                s0.x += __shfl_xor_sync(FULL, s0.x, o);
                s0.y += __shfl_xor_sync(FULL, s0.y, o);
                s0.z += __shfl_xor_sync(FULL, s0.z, o);
                s0.w += __shfl_xor_sync(FULL, s0.w, o);
                s1.x += __shfl_xor_sync(FULL, s1.x, o);
                s1.y += __shfl_xor_sync(FULL, s1.y, o);
                s1.z += __shfl_xor_sync(FULL, s1.z, o);
                s1.w += __shfl_xor_sync(FULL, s1.w, o);
                s2.x += __shfl_xor_sync(FULL, s2.x, o);
                s2.y += __shfl_xor_sync(FULL, s2.y, o);
                s2.z += __shfl_xor_sync(FULL, s2.z, o);
                s2.w += __shfl_xor_sync(FULL, s2.w, o);
            }
            if (l < 8) {
                float* r = red[wid][l];
                r[0] = d0; r[1] = d1; r[2] = d2;
                r[3] = s0.x; r[4] = s0.y; r[5] = s0.z; r[6] = s0.w;
                r[7] = s1.x; r[8] = s1.y; r[9] = s1.z; r[10] = s1.w;
                r[11] = s2.x; r[12] = s2.y; r[13] = s2.z; r[14] = s2.w;
            }
            __syncthreads();

            // 8 threads: cross-warp reduce + tanh -> h1sh[96]
            if (tid < 8) {
                float acc[15];
#pragma unroll
                for (int i = 0; i < 15; i++) acc[i] = 0.f;
#pragma unroll
                for (int w = 0; w < 8; w++) {
                    const float* r = red[w][tid];
#pragma unroll
                    for (int i = 0; i < 15; i++) acc[i] += r[i];
                }
                float rd0 = 1.f / (acc[0] + EPSV);
                float rd1 = 1.f / (acc[1] + EPSV);
                float rd2 = 1.f / (acc[2] + EPSV);
#pragma unroll
                for (int k = 0; k < 4; k++) {
                    int c = 4 * tid + k;
                    h1sh[c]      = tanhf(fmaf(acc[3 + k],  rd0, bias1[c]));
                    h1sh[32 + c] = tanhf(fmaf(acc[7 + k],  rd1, bias1[32 + c]));
                    h1sh[64 + c] = tanhf(fmaf(acc[11 + k], rd2, bias1[64 + c]));
                }
            }
            __syncthreads();

            // 96 threads: write h1 + fused xl2 = h1 @ Wl2 + bl2
            if (tid < 96) {
                float y = bl2[tid];
#pragma unroll 8
                for (int k = 0; k < 96; k++)
                    y = fmaf(h1sh[k], Wl2[k * 96 + tid], y);
                g_h1[(long)dst * 96 + tid]  = h1sh[tid];
                g_xl2[(long)dst * 96 + tid] = y;
            }
            __syncthreads();
        }
    }
    gridsync(nb);

    // ---- gat2 (+ inlined xr2) at pooled dsts (warp per dst) ----
    {
        int gwid = blockIdx.x * 8 + wid;
        int wstride = nb * 8;
        float a0 = att2[l], a1 = att2[32 + l], a2 = att2[64 + l];
        for (int gw = gwid; gw < GG; gw += wstride) {
            int dst = g_firstidx[gw];
            float h0 = g_h1[(long)dst * 96 + l];
            float h1v = g_h1[(long)dst * 96 + 32 + l];
            float h2 = g_h1[(long)dst * 96 + 64 + l];

            float q0 = br2[l], q1 = br2[32 + l], q2 = br2[64 + l];
#pragma unroll
            for (int kk = 0; kk < 32; kk++) {
                float hk = __shfl_sync(FULL, h0, kk);
                q0 = fmaf(hk, Wr2[kk * 96 + l],      q0);
                q1 = fmaf(hk, Wr2[kk * 96 + 32 + l], q1);
                q2 = fmaf(hk, Wr2[kk * 96 + 64 + l], q2);
            }
#pragma unroll
            for (int kk = 0; kk < 32; kk++) {
                float hk = __shfl_sync(FULL, h1v, kk);
                q0 = fmaf(hk, Wr2[(32 + kk) * 96 + l],      q0);
                q1 = fmaf(hk, Wr2[(32 + kk) * 96 + 32 + l], q1);
                q2 = fmaf(hk, Wr2[(32 + kk) * 96 + 64 + l], q2);
            }
#pragma unroll
            for (int kk = 0; kk < 32; kk++) {
                float hk = __shfl_sync(FULL, h2, kk);
                q0 = fmaf(hk, Wr2[(64 + kk) * 96 + l],      q0);
                q1 = fmaf(hk, Wr2[(64 + kk) * 96 + 32 + l], q1);
                q2 = fmaf(hk, Wr2[(64 + kk) * 96 + 64 + l], q2);
            }

            float d0 = 0.f, d1 = 0.f, d2 = 0.f;
            float s0 = 0.f, s1 = 0.f, s2 = 0.f;
            auto proc = [&](int src) {
                float v0 = g_xl2[(long)src * 96 + l];
                float v1 = g_xl2[(long)src * 96 + 32 + l];
                float v2 = g_xl2[(long)src * 96 + 64 + l];
                float p0 = leaky(v0 + q0) * a0;
                float p1 = leaky(v1 + q1) * a1;
                float p2 = leaky(v2 + q2) * a2;
#pragma unroll
                for (int o = 16; o; o >>= 1) {
                    p0 += __shfl_xor_sync(FULL, p0, o);
                    p1 += __shfl_xor_sync(FULL, p1, o);
                    p2 += __shfl_xor_sync(FULL, p2, o);
                }
                float e0 = __expf(p0), e1 = __expf(p1), e2 = __expf(p2);
                d0 += e0; d1 += e1; d2 += e2;
                s0 = fmaf(e0, v0, s0); s1 = fmaf(e1, v1, s1); s2 = fmaf(e2, v2, s2);
            };

            proc(dst);
            int en = min(g_counts[dst], DEGMAX);
            const int* lst = &g_ssrc2[dst * DEGMAX];
            for (int base = 0; base < en; base += 32) {
                int mine = (base + l < en) ? lst[base + l] : 0;
                int cnt2 = min(32, en - base);
                for (int j = 0; j < cnt2; j++)
                    proc(__shfl_sync(FULL, mine, j));
            }

            float o0 = s0 / (d0 + EPSV) + bias2[l];
            float o1 = s1 / (d1 + EPSV) + bias2[32 + l];
            float o2 = s2 / (d2 + EPSV) + bias2[64 + l];
            float* prr = &g_pooled[gw * 192];
            prr[l]      = h0;
            prr[32 + l] = h1v;
            prr[64 + l] = h2;
            prr[96 + l]       = tanhf(o0);
            prr[96 + 32 + l]  = tanhf(o1);
            prr[96 + 64 + l]  = tanhf(o2);
        }
    }
    gridsync(nb);

    // ---- fc8 (blocks 0..63) ----
    if (blockIdx.x < GG / 8) {
        int gbase = blockIdx.x * 8;
        for (int i = tid; i < 8 * 192; i += 256)
            pr[i / 192][i % 192] = g_pooled[gbase * 192 + i];
        __syncthreads();

        float s0[8], s1[8];
#pragma unroll
        for (int g = 0; g < 8; g++) { s0[g] = 0.f; s1[g] = 0.f; }
        for (int jj = tid; jj < HID; jj += 256) {
            float acc[8];
            float bj = bfc1[jj];
#pragma unroll
            for (int g = 0; g < 8; g++) acc[g] = bj;
            for (int k = 0; k < 192; k++) {
                float w = Wfc1[k * HID + jj];
#pragma unroll
                for (int g = 0; g < 8; g++) acc[g] = fmaf(pr[g][k], w, acc[g]);
            }
            float w20 = Wfc2[jj * 2 + 0], w21 = Wfc2[jj * 2 + 1];
#pragma unroll
            for (int g = 0; g < 8; g++) {
                float a = fmaxf(acc[g], 0.f);
                s0[g] = fmaf(a, w20, s0[g]);
                s1[g] = fmaf(a, w21, s1[g]);
            }
        }
#pragma unroll
        for (int o = 16; o; o >>= 1) {
#pragma unroll
            for (int g = 0; g < 8; g++) {
                s0[g] += __shfl_xor_sync(FULL, s0[g], o);
                s1[g] += __shfl_xor_sync(FULL, s1[g], o);
            }
        }
        if (l == 0) {
#pragma unroll
            for (int g = 0; g < 8; g++) {
                part[wid][g * 2 + 0] = s0[g];
                part[wid][g * 2 + 1] = s1[g];
            }
        }
        __syncthreads();
        if (tid < 16) {
            float v = 0.f;
#pragma unroll
            for (int w = 0; w < 8; w++) v += part[w][tid];
            slog[tid] = v;
        }
        __syncthreads();
        if (tid < 8) {
            float l0 = slog[tid * 2 + 0] + bfc2[0];
            float l1 = slog[tid * 2 + 1] + bfc2[1];
            float m = fmaxf(l0, l1);
            float lse = m + logf(expf(l0 - m) + expf(l1 - m));
            out[(gbase + tid) * 2 + 0] = l0 - lse;
            out[(gbase + tid) * 2 + 1] = l1 - lse;
        }
    }
}

// ---------------- launch -----------------------------------------------------
extern "C" void kernel_launch(void* const* d_in, const int* in_sizes, int n_in,
                              void* d_out, int out_size) {
    static int nb1 = 0, nb2 = 0;
    if (!nb1) {
        int dev = 0, nsm = 0, o1 = 0, o2 = 0;
        cudaGetDevice(&dev);
        cudaDeviceGetAttribute(&nsm, cudaDevAttrMultiProcessorCount, dev);
        if (nsm < 1) nsm = 148;
        cudaOccupancyMaxActiveBlocksPerMultiprocessor(&o1, k_build, 256, 0);
        cudaOccupancyMaxActiveBlocksPerMultiprocessor(&o2, k_gnn, 256, 0);
        if (o1 < 1) o1 = 1;
        if (o2 < 1) o2 = 1;
        nb1 = nsm * o1;
        nb2 = nsm * o2;
        if (nb1 > 2048) nb1 = 2048;
        if (nb2 > 2048) nb2 = 2048;
    }

    static const int esz[19] = {
        6400000, 12288, 96, 12288, 96, 96, 96,
        9216, 96, 9216, 96, 96, 96,
        98304, 512, 1024, 2, 3200000, 50000
    };
    int map_[19];
    bool ident = (n_in == 19);
    if (ident)
        for (int i = 0; i < 19; i++) if (in_sizes[i] != esz[i]) { ident = false; break; }
    if (ident) {
        for (int i = 0; i < 19; i++) map_[i] = i;
    } else {
        bool used[64] = {};
        for (int i = 0; i < 19; i++) {
            map_[i] = (i < n_in) ? i : 0;
            for (int j = 0; j < n_in && j < 64; j++)
                if (!used[j] && in_sizes[j] == esz[i]) { map_[i] = j; used[j] = true; break; }
        }
    }

    k_build<<<nb1, 256>>>(
        (const float*)d_in[map_[0]],
        (const float*)d_in[map_[1]], (const float*)d_in[map_[2]],
        (const float*)d_in[map_[3]], (const float*)d_in[map_[4]],
        (const int*)d_in[map_[17]],  (const int*)d_in[map_[18]], nb1);

    k_gnn<<<nb2, 256>>>(
        (const float*)d_in[map_[5]],  (const float*)d_in[map_[6]],
        (const float*)d_in[map_[7]],  (const float*)d_in[map_[8]],
        (const float*)d_in[map_[9]],  (const float*)d_in[map_[10]],
        (const float*)d_in[map_[11]], (const float*)d_in[map_[12]],
        (const float*)d_in[map_[13]], (const float*)d_in[map_[14]],
        (const float*)d_in[map_[15]], (const float*)d_in[map_[16]],
        (float*)d_out, nb2);
}

// round 17
// speedup vs baseline: 1.3906x; 1.3906x over previous
#include <cuda_runtime.h>
#include <cuda_bf16.h>

#define NN      50000
#define ECNT    1600000
#define INDIM   128
#define D1      96
#define GG      512
#define HID     512
#define NEG     0.2f
#define EPSV    1e-16f
#define DEGMAX  128
#define NMAX    20000
#define ESTORE  4096

// ---------------- device scratch ----------------
__device__ int   g_counts[NN];
__device__ int   g_ssrc2[NN * DEGMAX];
__device__ int   g_firstidx[GG];
__device__ int   g_poolslot[NN];
__device__ int   g_needed[NN];
__device__ int   g_list[NMAX];
__device__ int   g_ncnt;
__device__ int   g_task;
__device__ int   g_barArrive;
__device__ volatile unsigned g_barGen;

__device__ __align__(16) float g_xl1[NN * D1];
__device__ __align__(16) float g_xr1[NN * D1];
__device__ __align__(16) float g_h1 [NN * D1];
__device__ __align__(16) float g_xl2[NN * D1];

__device__ __forceinline__ float leaky(float t) { return t > 0.f ? t : NEG * t; }

__device__ __forceinline__ void gridsync(int nb) {
    __syncthreads();
    if (threadIdx.x == 0) {
        __threadfence();
        unsigned gen = g_barGen;
        if (atomicAdd(&g_barArrive, 1) == nb - 1) {
            g_barArrive = 0;
            __threadfence();
            g_barGen = gen + 1;
        } else {
            while (g_barGen == gen) __nanosleep(64);
        }
        __threadfence();
    }
    __syncthreads();
}

// ---------------- GEMM tile helpers ----------
__device__ void gemm_tile_full(const float* __restrict__ A, const float* __restrict__ B,
                               const float* __restrict__ bias, float* __restrict__ C,
                               int tile, int M, int K,
                               float (*As)[132], float (*Bs)[96]) {
    int tx = threadIdx.x & 15;
    int ty = threadIdx.x >> 4;
    int rowBase = tile * 128;
    float acc[8][6];
#pragma unroll
    for (int r = 0; r < 8; r++)
#pragma unroll
        for (int c = 0; c < 6; c++) acc[r][c] = 0.f;
    int lm = threadIdx.x >> 1;
    int lk = (threadIdx.x & 1) * 4;
    for (int kt = 0; kt < K; kt += 8) {
        int gr = rowBase + lm;
        float4 av = (gr < M) ? *(const float4*)&A[(long)gr * K + kt + lk]
                             : make_float4(0.f, 0.f, 0.f, 0.f);
        As[lk + 0][lm] = av.x; As[lk + 1][lm] = av.y;
        As[lk + 2][lm] = av.z; As[lk + 3][lm] = av.w;
#pragma unroll
        for (int j = 0; j < 3; j++) {
            int idx = threadIdx.x + 256 * j;
            Bs[idx / 96][idx % 96] = B[(kt + idx / 96) * 96 + idx % 96];
        }
        __syncthreads();
#pragma unroll
        for (int k = 0; k < 8; k++) {
            float a[8], bb[6];
#pragma unroll
            for (int r = 0; r < 8; r++) a[r] = As[k][ty + 16 * r];
#pragma unroll
            for (int c = 0; c < 6; c++) bb[c] = Bs[k][tx + 16 * c];
#pragma unroll
            for (int r = 0; r < 8; r++)
#pragma unroll
                for (int c = 0; c < 6; c++) acc[r][c] = fmaf(a[r], bb[c], acc[r][c]);
        }
        __syncthreads();
    }
#pragma unroll
    for (int r = 0; r < 8; r++) {
        int row = rowBase + ty + 16 * r;
        if (row < M) {
#pragma unroll
            for (int c = 0; c < 6; c++)
                C[(long)row * 96 + tx + 16 * c] = acc[r][c] + bias[tx + 16 * c];
        }
    }
}

__device__ void gemm_tile_gather(const float* __restrict__ A, const float* __restrict__ B,
                                 const float* __restrict__ bias, float* __restrict__ C,
                                 int tile, int cnt, int K,
                                 float (*As)[132], float (*Bs)[96], int* rows) {
    int tx = threadIdx.x & 15;
    int ty = threadIdx.x >> 4;
    int rowBase = tile * 128;
    if (threadIdx.x < 128) {
        int r = rowBase + threadIdx.x;
        rows[threadIdx.x] = (r < cnt) ? g_list[r] : -1;
    }
    __syncthreads();
    float acc[8][6];
#pragma unroll
    for (int r = 0; r < 8; r++)
#pragma unroll
        for (int c = 0; c < 6; c++) acc[r][c] = 0.f;
    int lm = threadIdx.x >> 1;
    int lk = (threadIdx.x & 1) * 4;
    for (int kt = 0; kt < K; kt += 8) {
        int nd = rows[lm];
        float4 av = (nd >= 0) ? *(const float4*)&A[(long)nd * K + kt + lk]
                              : make_float4(0.f, 0.f, 0.f, 0.f);
        As[lk + 0][lm] = av.x; As[lk + 1][lm] = av.y;
        As[lk + 2][lm] = av.z; As[lk + 3][lm] = av.w;
#pragma unroll
        for (int j = 0; j < 3; j++) {
            int idx = threadIdx.x + 256 * j;
            Bs[idx / 96][idx % 96] = B[(kt + idx / 96) * 96 + idx % 96];
        }
        __syncthreads();
#pragma unroll
        for (int k = 0; k < 8; k++) {
            float a[8], bb[6];
#pragma unroll
            for (int r = 0; r < 8; r++) a[r] = As[k][ty + 16 * r];
#pragma unroll
            for (int c = 0; c < 6; c++) bb[c] = Bs[k][tx + 16 * c];
#pragma unroll
            for (int r = 0; r < 8; r++)
#pragma unroll
                for (int c = 0; c < 6; c++) acc[r][c] = fmaf(a[r], bb[c], acc[r][c]);
        }
        __syncthreads();
    }
#pragma unroll
    for (int r = 0; r < 8; r++) {
        int nd = rows[ty + 16 * r];
        if (nd >= 0) {
#pragma unroll
            for (int c = 0; c < 6; c++)
                C[(long)nd * 96 + tx + 16 * c] = acc[r][c] + bias[tx + 16 * c];
        }
    }
}

// ================= KERNEL 1: build (R14 verbatim) =====================
__global__ __launch_bounds__(256)
void k_build(const float* __restrict__ x,
             const float* __restrict__ Wl1, const float* __restrict__ bl1,
             const float* __restrict__ Wr1, const float* __restrict__ br1,
             const int* __restrict__ ei, const int* __restrict__ batch, int nb) {
    __shared__ float sh[1824];
    __shared__ int rows[128];
    __shared__ int s_task;
    float (*As)[132] = (float(*)[132])sh;
    float (*Bs)[96]  = (float(*)[96])(sh + 1056);

    int tid = threadIdx.x;
    int gtid = blockIdx.x * blockDim.x + tid;
    int gstride = nb * blockDim.x;

    for (int i = gtid; i < NN; i += gstride) {
        g_counts[i] = 0;
        int b = batch[i];
        int pooled = (i == 0) || (batch[i - 1] != b);
        g_needed[i] = pooled;
        if (pooled) {
            g_firstidx[b] = i;
            g_poolslot[i] = b;
            g_list[b] = i;
        } else {
            g_poolslot[i] = -1;
        }
    }
    if (gtid == 0) { g_ncnt = GG; g_task = 0; }
    gridsync(nb);

    {
        const int4* s4 = (const int4*)ei;
        const int4* d4 = (const int4*)(ei + ECNT);
        for (int e4 = gtid; e4 < ECNT / 4; e4 += gstride) {
            int4 dd = d4[e4];
            int4 ss = s4[e4];
            int d[4] = {dd.x, dd.y, dd.z, dd.w};
            int s[4] = {ss.x, ss.y, ss.z, ss.w};
#pragma unroll
            for (int k = 0; k < 4; k++) {
                if (g_poolslot[d[k]] >= 0) {
                    if (atomicExch(&g_needed[s[k]], 1) == 0) {
                        int p = atomicAdd(&g_ncnt, 1);
                        if (p < NMAX) g_list[p] = s[k];
                    }
                }
            }
        }
    }
    gridsync(nb);

    {
        int cnt = min(g_ncnt, NMAX);
        const int T1 = (NN + 127) / 128;
        int T2 = (cnt + 127) / 128;
        const int SC = (ECNT + ESTORE - 1) / ESTORE;
        int total = T1 + T2 + SC;
        const int4* s4 = (const int4*)ei;
        const int4* d4 = (const int4*)(ei + ECNT);
        for (;;) {
            __syncthreads();
            if (tid == 0) s_task = atomicAdd(&g_task, 1);
            __syncthreads();
            int t = s_task;
            if (t >= total) break;
            if (t < T1) {
                gemm_tile_full(x, Wl1, bl1, g_xl1, t, NN, INDIM, As, Bs);
            } else if (t < T1 + T2) {
                gemm_tile_gather(x, Wr1, br1, g_xr1, t - T1, cnt, INDIM, As, Bs, rows);
            } else {
                int base4 = (t - T1 - T2) * (ESTORE / 4);
#pragma unroll
                for (int k = 0; k < 4; k++) {
                    int e4 = base4 + k * 256 + tid;
                    if (e4 < ECNT / 4) {
                        int4 dd = d4[e4];
                        int4 ss = s4[e4];
                        int d[4] = {dd.x, dd.y, dd.z, dd.w};
                        int s[4] = {ss.x, ss.y, ss.z, ss.w};
#pragma unroll
                        for (int j = 0; j < 4; j++) {
                            if (g_needed[d[j]]) {
                                int p = atomicAdd(&g_counts[d[j]], 1);
                                if (p < DEGMAX) g_ssrc2[d[j] * DEGMAX + p] = s[j];
                            }
                        }
                    }
                }
            }
        }
    }
}

// ================= KERNEL 2: GNN — R14 gat1 + merged gat2/fc8 ===============
__global__ __launch_bounds__(256, 3)
void k_gnn(const float* __restrict__ att1, const float* __restrict__ bias1,
           const float* __restrict__ Wl2,  const float* __restrict__ bl2,
           const float* __restrict__ Wr2,  const float* __restrict__ br2,
           const float* __restrict__ att2, const float* __restrict__ bias2,
           const float* __restrict__ Wfc1, const float* __restrict__ bfc1,
           const float* __restrict__ Wfc2, const float* __restrict__ bfc2,
           float* __restrict__ out, int nb) {
    __shared__ float sh[1680];
    float (*pr)[192]  = (float(*)[192])sh;           // 8 pooled rows (smem only)
    float (*part)[16] = (float(*)[16])(sh + 1536);
    float* slog       = sh + 1664;

    int tid = threadIdx.x;
    int wid = tid >> 5, l = tid & 31;
    int gwid = blockIdx.x * 8 + wid;
    int wstride = nb * 8;
    const unsigned FULL = 0xffffffffu;

    // ---- gat1 + fused xl2 : 8 lanes/edge, 4 edges in flight (R14 verbatim) ----
    {
        int cnt = min(g_ncnt, NMAX);
        int u = l & 7;
        int grp = l >> 3;
        const float4* att4 = (const float4*)att1;
        float4 A0 = att4[u], A1 = att4[8 + u], A2 = att4[16 + u];
        const float4* b4 = (const float4*)bias1;
        float4 B0 = b4[u], B1 = b4[8 + u], B2 = b4[16 + u];
        const float4* xl4 = (const float4*)g_xl1;
        const float4* xr4 = (const float4*)g_xr1;

        for (int gw = gwid; gw < cnt; gw += wstride) {
            int dst = g_list[gw];
            float4 q0 = xr4[(long)dst * 24 + u];
            float4 q1 = xr4[(long)dst * 24 + 8 + u];
            float4 q2 = xr4[(long)dst * 24 + 16 + u];

            float d0 = 0.f, d1 = 0.f, d2 = 0.f;
            float4 s0 = {0,0,0,0}, s1 = {0,0,0,0}, s2 = {0,0,0,0};

            auto edge4 = [&](int src, bool valid) {
                const float4* row = xl4 + (long)src * 24;
                float4 v0 = row[u], v1 = row[8 + u], v2 = row[16 + u];
                float p0 = leaky(v0.x + q0.x) * A0.x + leaky(v0.y + q0.y) * A0.y
                         + leaky(v0.z + q0.z) * A0.z + leaky(v0.w + q0.w) * A0.w;
                float p1 = leaky(v1.x + q1.x) * A1.x + leaky(v1.y + q1.y) * A1.y
                         + leaky(v1.z + q1.z) * A1.z + leaky(v1.w + q1.w) * A1.w;
                float p2 = leaky(v2.x + q2.x) * A2.x + leaky(v2.y + q2.y) * A2.y
                         + leaky(v2.z + q2.z) * A2.z + leaky(v2.w + q2.w) * A2.w;
#pragma unroll
                for (int o = 4; o; o >>= 1) {
                    p0 += __shfl_xor_sync(FULL, p0, o);
                    p1 += __shfl_xor_sync(FULL, p1, o);
                    p2 += __shfl_xor_sync(FULL, p2, o);
                }
                float e0 = valid ? __expf(p0) : 0.f;
                float e1 = valid ? __expf(p1) : 0.f;
                float e2 = valid ? __expf(p2) : 0.f;
                d0 += e0; d1 += e1; d2 += e2;
                s0.x = fmaf(e0, v0.x, s0.x); s0.y = fmaf(e0, v0.y, s0.y);
                s0.z = fmaf(e0, v0.z, s0.z); s0.w = fmaf(e0, v0.w, s0.w);
                s1.x = fmaf(e1, v1.x, s1.x); s1.y = fmaf(e1, v1.y, s1.y);
                s1.z = fmaf(e1, v1.z, s1.z); s1.w = fmaf(e1, v1.w, s1.w);
                s2.x = fmaf(e2, v2.x, s2.x); s2.y = fmaf(e2, v2.y, s2.y);
                s2.z = fmaf(e2, v2.z, s2.z); s2.w = fmaf(e2, v2.w, s2.w);
            };

            edge4(dst, grp == 0);
            int en = min(g_counts[dst], DEGMAX);
            const int* lst = &g_ssrc2[dst * DEGMAX];
            for (int base = 0; base < en; base += 32) {
                int mine = (base + l < en) ? lst[base + l] : 0;
                int rem = en - base;
#pragma unroll
                for (int j = 0; j < 8; j++) {
                    if (j * 4 >= rem) break;
                    int idx = j * 4 + grp;
                    int src = __shfl_sync(FULL, mine, idx);
                    edge4(src, idx < rem);
                }
            }

#pragma unroll
            for (int o = 8; o <= 16; o <<= 1) {
                d0 += __shfl_xor_sync(FULL, d0, o);
                d1 += __shfl_xor_sync(FULL, d1, o);
                d2 += __shfl_xor_sync(FULL, d2, o);
                s0.x += __shfl_xor_sync(FULL, s0.x, o);
                s0.y += __shfl_xor_sync(FULL, s0.y, o);
                s0.z += __shfl_xor_sync(FULL, s0.z, o);
                s0.w += __shfl_xor_sync(FULL, s0.w, o);
                s1.x += __shfl_xor_sync(FULL, s1.x, o);
                s1.y += __shfl_xor_sync(FULL, s1.y, o);
                s1.z += __shfl_xor_sync(FULL, s1.z, o);
                s1.w += __shfl_xor_sync(FULL, s1.w, o);
                s2.x += __shfl_xor_sync(FULL, s2.x, o);
                s2.y += __shfl_xor_sync(FULL, s2.y, o);
                s2.z += __shfl_xor_sync(FULL, s2.z, o);
                s2.w += __shfl_xor_sync(FULL, s2.w, o);
            }

            float rd0 = 1.f / (d0 + EPSV);
            float rd1 = 1.f / (d1 + EPSV);
            float rd2 = 1.f / (d2 + EPSV);
            float4 t0, t1, t2;
            t0.x = tanhf(fmaf(s0.x, rd0, B0.x)); t0.y = tanhf(fmaf(s0.y, rd0, B0.y));
            t0.z = tanhf(fmaf(s0.z, rd0, B0.z)); t0.w = tanhf(fmaf(s0.w, rd0, B0.w));
            t1.x = tanhf(fmaf(s1.x, rd1, B1.x)); t1.y = tanhf(fmaf(s1.y, rd1, B1.y));
            t1.z = tanhf(fmaf(s1.z, rd1, B1.z)); t1.w = tanhf(fmaf(s1.w, rd1, B1.w));
            t2.x = tanhf(fmaf(s2.x, rd2, B2.x)); t2.y = tanhf(fmaf(s2.y, rd2, B2.y));
            t2.z = tanhf(fmaf(s2.z, rd2, B2.z)); t2.w = tanhf(fmaf(s2.w, rd2, B2.w));

            float hv0 = 0.f, hv1 = 0.f, hv2 = 0.f;
            float y0 = bl2[l], y1 = bl2[32 + l], y2 = bl2[64 + l];
#pragma unroll
            for (int kk = 0; kk < 32; kk++) {
                const int su = kk >> 2;
                float c0, c1, c2;
                switch (kk & 3) {
                    case 0: c0 = t0.x; c1 = t1.x; c2 = t2.x; break;
                    case 1: c0 = t0.y; c1 = t1.y; c2 = t2.y; break;
                    case 2: c0 = t0.z; c1 = t1.z; c2 = t2.z; break;
                    default: c0 = t0.w; c1 = t1.w; c2 = t2.w; break;
                }
                float hk0 = __shfl_sync(FULL, c0, su);
                float hk1 = __shfl_sync(FULL, c1, su);
                float hk2 = __shfl_sync(FULL, c2, su);
                if (l == kk) { hv0 = hk0; hv1 = hk1; hv2 = hk2; }
                y0 = fmaf(hk0, Wl2[kk * 96 + l],            y0);
                y1 = fmaf(hk0, Wl2[kk * 96 + 32 + l],       y1);
                y2 = fmaf(hk0, Wl2[kk * 96 + 64 + l],       y2);
                y0 = fmaf(hk1, Wl2[(32 + kk) * 96 + l],      y0);
                y1 = fmaf(hk1, Wl2[(32 + kk) * 96 + 32 + l], y1);
                y2 = fmaf(hk1, Wl2[(32 + kk) * 96 + 64 + l], y2);
                y0 = fmaf(hk2, Wl2[(64 + kk) * 96 + l],      y0);
                y1 = fmaf(hk2, Wl2[(64 + kk) * 96 + 32 + l], y1);
                y2 = fmaf(hk2, Wl2[(64 + kk) * 96 + 64 + l], y2);
            }
            g_h1[(long)dst * 96 + l]      = hv0;
            g_h1[(long)dst * 96 + 32 + l] = hv1;
            g_h1[(long)dst * 96 + 64 + l] = hv2;
            g_xl2[(long)dst * 96 + l]      = y0;
            g_xl2[(long)dst * 96 + 32 + l] = y1;
            g_xl2[(long)dst * 96 + 64 + l] = y2;
        }
    }
    gridsync(nb);

    // ---- merged gat2 + fc8 on blocks 0..63 (warp w <-> graph 8b+w) ----
    if (blockIdx.x >= GG / 8) return;
    {
        int g = blockIdx.x * 8 + wid;   // this warp's graph
        float a0 = att2[l], a1 = att2[32 + l], a2 = att2[64 + l];
        int dst = g_firstidx[g];
        float h0 = g_h1[(long)dst * 96 + l];
        float h1v = g_h1[(long)dst * 96 + 32 + l];
        float h2 = g_h1[(long)dst * 96 + 64 + l];

        float q0 = br2[l], q1 = br2[32 + l], q2 = br2[64 + l];
#pragma unroll
        for (int kk = 0; kk < 32; kk++) {
            float hk = __shfl_sync(FULL, h0, kk);
            q0 = fmaf(hk, Wr2[kk * 96 + l],      q0);
            q1 = fmaf(hk, Wr2[kk * 96 + 32 + l], q1);
            q2 = fmaf(hk, Wr2[kk * 96 + 64 + l], q2);
        }
#pragma unroll
        for (int kk = 0; kk < 32; kk++) {
            float hk = __shfl_sync(FULL, h1v, kk);
            q0 = fmaf(hk, Wr2[(32 + kk) * 96 + l],      q0);
            q1 = fmaf(hk, Wr2[(32 + kk) * 96 + 32 + l], q1);
            q2 = fmaf(hk, Wr2[(32 + kk) * 96 + 64 + l], q2);
        }
#pragma unroll
        for (int kk = 0; kk < 32; kk++) {
            float hk = __shfl_sync(FULL, h2, kk);
            q0 = fmaf(hk, Wr2[(64 + kk) * 96 + l],      q0);
            q1 = fmaf(hk, Wr2[(64 + kk) * 96 + 32 + l], q1);
            q2 = fmaf(hk, Wr2[(64 + kk) * 96 + 64 + l], q2);
        }

        float d0 = 0.f, d1 = 0.f, d2 = 0.f;
        float s0 = 0.f, s1 = 0.f, s2 = 0.f;
        auto proc = [&](int src) {
            float v0 = g_xl2[(long)src * 96 + l];
            float v1 = g_xl2[(long)src * 96 + 32 + l];
            float v2 = g_xl2[(long)src * 96 + 64 + l];
            float p0 = leaky(v0 + q0) * a0;
            float p1 = leaky(v1 + q1) * a1;
            float p2 = leaky(v2 + q2) * a2;
#pragma unroll
            for (int o = 16; o; o >>= 1) {
                p0 += __shfl_xor_sync(FULL, p0, o);
                p1 += __shfl_xor_sync(FULL, p1, o);
                p2 += __shfl_xor_sync(FULL, p2, o);
            }
            float e0 = __expf(p0), e1 = __expf(p1), e2 = __expf(p2);
            d0 += e0; d1 += e1; d2 += e2;
            s0 = fmaf(e0, v0, s0); s1 = fmaf(e1, v1, s1); s2 = fmaf(e2, v2, s2);
        };

        proc(dst);
        int en = min(g_counts[dst], DEGMAX);
        const int* lst = &g_ssrc2[dst * DEGMAX];
        for (int base = 0; base < en; base += 32) {
            int mine = (base + l < en) ? lst[base + l] : 0;
            int cnt2 = min(32, en - base);
            for (int j = 0; j < cnt2; j++)
                proc(__shfl_sync(FULL, mine, j));
        }

        float o0 = s0 / (d0 + EPSV) + bias2[l];
        float o1 = s1 / (d1 + EPSV) + bias2[32 + l];
        float o2 = s2 / (d2 + EPSV) + bias2[64 + l];
        // pooled row straight into shared memory (no global round-trip)
        pr[wid][l]       = h0;
        pr[wid][32 + l]  = h1v;
        pr[wid][64 + l]  = h2;
        pr[wid][96 + l]       = tanhf(o0);
        pr[wid][96 + 32 + l]  = tanhf(o1);
        pr[wid][96 + 64 + l]  = tanhf(o2);
    }
    __syncthreads();

    // ---- fc8 (same block) ----
    {
        int gbase = blockIdx.x * 8;
        float s0[8], s1[8];
#pragma unroll
        for (int g = 0; g < 8; g++) { s0[g] = 0.f; s1[g] = 0.f; }
        for (int jj = tid; jj < HID; jj += 256) {
            float acc[8];
            float bj = bfc1[jj];
#pragma unroll
            for (int g = 0; g < 8; g++) acc[g] = bj;
            for (int k = 0; k < 192; k++) {
                float w = Wfc1[k * HID + jj];
#pragma unroll
                for (int g = 0; g < 8; g++) acc[g] = fmaf(pr[g][k], w, acc[g]);
            }
            float w20 = Wfc2[jj * 2 + 0], w21 = Wfc2[jj * 2 + 1];
#pragma unroll
            for (int g = 0; g < 8; g++) {
                float a = fmaxf(acc[g], 0.f);
                s0[g] = fmaf(a, w20, s0[g]);
                s1[g] = fmaf(a, w21, s1[g]);
            }
        }
#pragma unroll
        for (int o = 16; o; o >>= 1) {
#pragma unroll
            for (int g = 0; g < 8; g++) {
                s0[g] += __shfl_xor_sync(FULL, s0[g], o);
                s1[g] += __shfl_xor_sync(FULL, s1[g], o);
            }
        }
        if (l == 0) {
#pragma unroll
            for (int g = 0; g < 8; g++) {
                part[wid][g * 2 + 0] = s0[g];
                part[wid][g * 2 + 1] = s1[g];
            }
        }
        __syncthreads();
        if (tid < 16) {
            float v = 0.f;
#pragma unroll
            for (int w = 0; w < 8; w++) v += part[w][tid];
            slog[tid] = v;
        }
        __syncthreads();
        if (tid < 8) {
            float l0 = slog[tid * 2 + 0] + bfc2[0];
            float l1 = slog[tid * 2 + 1] + bfc2[1];
            float m = fmaxf(l0, l1);
            float lse = m + logf(expf(l0 - m) + expf(l1 - m));
            out[(gbase + tid) * 2 + 0] = l0 - lse;
            out[(gbase + tid) * 2 + 1] = l1 - lse;
        }
    }
}

// ---------------- launch -----------------------------------------------------
extern "C" void kernel_launch(void* const* d_in, const int* in_sizes, int n_in,
                              void* d_out, int out_size) {
    static int nb1 = 0, nb2 = 0;
    if (!nb1) {
        int dev = 0, nsm = 0, o1 = 0, o2 = 0;
        cudaGetDevice(&dev);
        cudaDeviceGetAttribute(&nsm, cudaDevAttrMultiProcessorCount, dev);
        if (nsm < 1) nsm = 148;
        cudaOccupancyMaxActiveBlocksPerMultiprocessor(&o1, k_build, 256, 0);
        cudaOccupancyMaxActiveBlocksPerMultiprocessor(&o2, k_gnn, 256, 0);
        if (o1 < 1) o1 = 1;
        if (o2 < 1) o2 = 1;
        nb1 = nsm * o1;
        nb2 = nsm * o2;
        if (nb1 > 2048) nb1 = 2048;
        if (nb2 > 2048) nb2 = 2048;
    }

    static const int esz[19] = {
        6400000, 12288, 96, 12288, 96, 96, 96,
        9216, 96, 9216, 96, 96, 96,
        98304, 512, 1024, 2, 3200000, 50000
    };
    int map_[19];
    bool ident = (n_in == 19);
    if (ident)
        for (int i = 0; i < 19; i++) if (in_sizes[i] != esz[i]) { ident = false; break; }
    if (ident) {
        for (int i = 0; i < 19; i++) map_[i] = i;
    } else {
        bool used[64] = {};
        for (int i = 0; i < 19; i++) {
            map_[i] = (i < n_in) ? i : 0;
            for (int j = 0; j < n_in && j < 64; j++)
                if (!used[j] && in_sizes[j] == esz[i]) { map_[i] = j; used[j] = true; break; }
        }
    }

    k_build<<<nb1, 256>>>(
        (const float*)d_in[map_[0]],
        (const float*)d_in[map_[1]], (const float*)d_in[map_[2]],
        (const float*)d_in[map_[3]], (const float*)d_in[map_[4]],
        (const int*)d_in[map_[17]],  (const int*)d_in[map_[18]], nb1);

    k_gnn<<<nb2, 256>>>(
        (const float*)d_in[map_[5]],  (const float*)d_in[map_[6]],
        (const float*)d_in[map_[7]],  (const float*)d_in[map_[8]],
        (const float*)d_in[map_[9]],  (const float*)d_in[map_[10]],
        (const float*)d_in[map_[11]], (const float*)d_in[map_[12]],
        (const float*)d_in[map_[13]], (const float*)d_in[map_[14]],
        (const float*)d_in[map_[15]], (const float*)d_in[map_[16]],
        (float*)d_out, nb2);
}